// round 11
// baseline (speedup 1.0000x reference)
#include <cuda_runtime.h>
#include <cuda_bf16.h>
#include <cstdint>

// ---------------------------------------------------------------------------
// FactorizedSoftmaxV2, R10: int8 IMMA (mma.sync m16n8k32.s8) for the LSE GEMM.
// fp8 QMMA proved half-rate per instruction (same FLOP/s as bf16); int8 IMMA
// is historically 2x the fp16-class rate. Same tiles/layout as R8/R9.
//   nll[t] = (lse3 - s_cluster) + (log sumexp(z_int8) - z_tgt_fp32)
//   z = (qx . qb) / (SX*SB),  SX=24, SB=1024
// ---------------------------------------------------------------------------

#define MAX_TOK 4096
#define HID 1024
#define NCL 3
#define MAX_VOCAB 50257
#define SX 24.0f
#define SB 1024.0f
#define INV_SCALE (1.0f / (24.0f * 1024.0f))

__device__ int    g_order[NCL * MAX_TOK];
__device__ int    g_counts[NCL];
__device__ float  g_rownll[MAX_TOK];
__device__ float  g_sumexp[MAX_TOK];
__device__ float  g_tgt[MAX_TOK];
__device__ int8_t g_A8[(size_t)NCL * MAX_TOK * HID];      // 12 MB
__device__ int8_t g_B8[(size_t)MAX_VOCAB * HID];          // ~51 MB

__device__ __forceinline__ int cluster_of(int yy) {
    return yy < 20000 ? 0 : (yy < 40000 ? 1 : 2);
}

// ---------------- PTX helpers (baseline PTX only) ----------------
__device__ __forceinline__ uint32_t smem_u32(const void* p) {
    uint32_t a;
    asm("{ .reg .u64 t; cvta.to.shared.u64 t, %1; cvt.u32.u64 %0, t; }"
        : "=r"(a) : "l"(p));
    return a;
}
__device__ __forceinline__ void cp16(uint32_t dst, const void* src) {
    size_t g = __cvta_generic_to_global(src);
    asm volatile("cp.async.cg.shared.global [%0], [%1], 16;"
                 :: "r"(dst), "l"(g) : "memory");
}
#define CP_COMMIT() asm volatile("cp.async.commit_group;" ::: "memory")

__device__ __forceinline__ void ldm_x4(uint32_t* r, uint32_t addr) {
    asm volatile("ldmatrix.sync.aligned.m8n8.x4.shared.b16 {%0,%1,%2,%3}, [%4];"
                 : "=r"(r[0]), "=r"(r[1]), "=r"(r[2]), "=r"(r[3]) : "r"(addr));
}
__device__ __forceinline__ void mma_s8(int* d, const uint32_t* a,
                                       const uint32_t* b) {
    asm volatile(
        "mma.sync.aligned.m16n8k32.row.col.s32.s8.s8.s32 "
        "{%0,%1,%2,%3}, {%4,%5,%6,%7}, {%8,%9}, {%0,%1,%2,%3};"
        : "+r"(d[0]), "+r"(d[1]), "+r"(d[2]), "+r"(d[3])
        : "r"(a[0]), "r"(a[1]), "r"(a[2]), "r"(a[3]), "r"(b[0]), "r"(b[1]));
}

__device__ __forceinline__ int8_t q8(float v, float scale) {
    float s = fminf(fmaxf(v * scale, -127.f), 127.f);
    return (int8_t)__float2int_rn(s);
}

// ---------------------------------------------------------------------------
// L0: logits [1024][vocab] f32 -> g_B8 [vocab][1024] s8 (x1024). Zeros counts.
// ---------------------------------------------------------------------------
__global__ void k_convert_B(const float* __restrict__ logits, int vocab) {
    __shared__ float tile[64][33];
    if (blockIdx.x == 0 && blockIdx.y == 0 && threadIdx.x < NCL)
        g_counts[threadIdx.x] = 0;
    const int nb = blockIdx.x * 32;
    const int kb = blockIdx.y * 64;
    const int tid = threadIdx.x;
#pragma unroll
    for (int j = 0; j < 8; j++) {
        int idx = tid + j * 256;
        int k = idx >> 5, n = idx & 31;
        tile[k][n] = (nb + n < vocab)
            ? logits[(size_t)(kb + k) * vocab + nb + n] : 0.f;
    }
    __syncthreads();
    const int n_loc = tid >> 3;
    const int kq = (tid & 7) * 8;
    const int n = nb + n_loc;
    if (n < vocab) {
        int8_t w[8];
#pragma unroll
        for (int i = 0; i < 8; i++)
            w[i] = q8(tile[kq + i][n_loc], SB);
        *(uint2*)(g_B8 + (size_t)n * HID + kb + kq) = *(uint2*)w;
    }
}

// ---------------------------------------------------------------------------
// L1: cluster head (fp32) + atomic bucketing + zero sumexp
// ---------------------------------------------------------------------------
__global__ void k_cluster_bucket(const float* __restrict__ x,
                                 const int* __restrict__ y,
                                 const float* __restrict__ Wc, int n) {
    int warp = (blockIdx.x * blockDim.x + threadIdx.x) >> 5;
    int lane = threadIdx.x & 31;
    if (warp >= n) return;
    const float* xr = x + (size_t)warp * HID;
    float s0 = 0.f, s1 = 0.f, s2 = 0.f;
    for (int k = lane; k < HID; k += 32) {
        float xv = xr[k];
        s0 += xv * Wc[k];
        s1 += xv * Wc[HID + k];
        s2 += xv * Wc[2 * HID + k];
    }
#pragma unroll
    for (int m = 16; m; m >>= 1) {
        s0 += __shfl_xor_sync(0xffffffffu, s0, m);
        s1 += __shfl_xor_sync(0xffffffffu, s1, m);
        s2 += __shfl_xor_sync(0xffffffffu, s2, m);
    }
    if (lane == 0) {
        int cy = cluster_of(y[warp]);
        float mx = fmaxf(s0, fmaxf(s1, s2));
        float lse = logf(expf(s0 - mx) + expf(s1 - mx) + expf(s2 - mx)) + mx;
        float sc = (cy == 0) ? s0 : ((cy == 1) ? s1 : s2);
        g_rownll[warp] = lse - sc;
        g_sumexp[warp] = 0.f;
        int slot = atomicAdd(&g_counts[cy], 1);
        g_order[cy * MAX_TOK + slot] = warp;
    }
}

// ---------------------------------------------------------------------------
// L2: gather+quantize x rows -> g_A8 s8 (x24, bucketed). grid (MAX_TOK, 3).
// ---------------------------------------------------------------------------
__global__ void k_convert_x(const float* __restrict__ x) {
    const int c = blockIdx.y;
    const int r = blockIdx.x;
    if (r >= g_counts[c]) return;
    const int t = g_order[c * MAX_TOK + r];
    const float4* src = (const float4*)(x + (size_t)t * HID);
    int8_t* dst = g_A8 + (size_t)(c * MAX_TOK + r) * HID;
    const int j = threadIdx.x;           // 0..127
    float4 v0 = src[j * 2];
    float4 v1 = src[j * 2 + 1];
    int8_t w[8];
    w[0] = q8(v0.x, SX); w[1] = q8(v0.y, SX);
    w[2] = q8(v0.z, SX); w[3] = q8(v0.w, SX);
    w[4] = q8(v1.x, SX); w[5] = q8(v1.y, SX);
    w[6] = q8(v1.z, SX); w[7] = q8(v1.w, SX);
    *(uint2*)(dst + j * 8) = *(uint2*)w;
}

// ---------------------------------------------------------------------------
// L3: main GEMM. CTA 128(M)x256(N), BK=64 s8, 512 threads (16 warps),
// warp tile 32x64 via m16n8k32.s8. 3-stage cp.async pipeline.
// Row layout: 80 B (64 data + 16 pad) -> conflict-free ldmatrix.
// ---------------------------------------------------------------------------
#define BK 64
#define ROWB 80
#define ABYTES (128 * ROWB)             // 10240
#define BBYTES (256 * ROWB)             // 20480
#define STAGE (ABYTES + BBYTES)         // 30720
#define SMEM_DYN (3 * STAGE)            // 92160
#define NTHR 512

struct TA { int abase, row0, count, l, col0, vocab; };

__device__ __forceinline__ void load_tile(uint32_t sb, int it, int stage,
                                          int tid, const TA& ta) {
    const int k0 = it * BK;
    const uint32_t As = sb + stage * STAGE;
    const uint32_t Bs = As + ABYTES;
    {
        int row = tid >> 2, cc = tid & 3;
        int rl = ta.row0 + row;
        int ridx = ta.abase + (rl < ta.count ? rl : ta.count - 1);
        cp16(As + row * ROWB + cc * 16,
             g_A8 + (size_t)ridx * HID + k0 + cc * 16);
    }
#pragma unroll
    for (int j = 0; j < 2; j++) {
        int q = tid + j * NTHR;
        int row = q >> 2, cc = q & 3;
        int col = ta.l + ta.col0 + row;
        if (col >= ta.vocab) col = ta.vocab - 1;
        cp16(Bs + row * ROWB + cc * 16,
             g_B8 + (size_t)col * HID + k0 + cc * 16);
    }
    CP_COMMIT();
}

__global__ __launch_bounds__(NTHR, 1)
void k_main_mma(int vocab) {
    extern __shared__ char dsm[];
    __shared__ int stok[128];

    const int c = blockIdx.z;
    const int l = (c == 0) ? 0 : ((c == 1) ? 20000 : 40000);
    const int r = (c == 0) ? 20000 : ((c == 1) ? 40000 : vocab);
    const int ncols = r - l;
    const int col0 = blockIdx.x * 256;
    if (col0 >= ncols) return;
    const int count = g_counts[c];
    const int row0 = blockIdx.y * 128;
    if (row0 >= count) return;
    const int abase = c * MAX_TOK;

    const int tid = threadIdx.x;
    const int lane = tid & 31;
    const int wid = tid >> 5;
    const int warp_m = wid & 3;      // 0..3  (32-row slab)
    const int warp_n = wid >> 2;     // 0..3  (64-col slab)

    const uint32_t sb = smem_u32(dsm);

    if (tid < 128) {
        int rl = row0 + tid;
        stok[tid] = g_order[abase + (rl < count ? rl : count - 1)];
    }
    __syncthreads();

    TA ta{abase, row0, count, l, col0, vocab};

    int acc[2][8][4];
#pragma unroll
    for (int i = 0; i < 2; i++)
#pragma unroll
        for (int j = 0; j < 8; j++)
#pragma unroll
            for (int q = 0; q < 4; q++) acc[i][j][q] = 0;

    load_tile(sb, 0, 0, tid, ta);
    load_tile(sb, 1, 1, tid, ta);

    const uint32_t a_off = (warp_m * 32 + (lane & 15)) * ROWB + (lane >> 4) * 16;
    const uint32_t b_off = (warp_n * 64 + ((lane >> 4) << 3) + (lane & 7)) * ROWB +
                           ((lane >> 3) & 1) * 16;

    const int KIT = HID / BK;  // 16
    for (int it = 0; it < KIT; it++) {
        if (it < KIT - 1)
            asm volatile("cp.async.wait_group 1;" ::: "memory");
        else
            asm volatile("cp.async.wait_group 0;" ::: "memory");
        __syncthreads();
        if (it + 2 < KIT) load_tile(sb, it + 2, (it + 2) % 3, tid, ta);

        const uint32_t As = sb + (it % 3) * STAGE + a_off;
        const uint32_t Bs = sb + (it % 3) * STAGE + ABYTES + b_off;
#pragma unroll
        for (int kk = 0; kk < 2; kk++) {    // 32 s8 k-elems each
            uint32_t af[2][4], bf[8][2];
#pragma unroll
            for (int mf = 0; mf < 2; mf++)
                ldm_x4(af[mf], As + mf * (16 * ROWB) + kk * 32);
#pragma unroll
            for (int np = 0; np < 4; np++) {
                uint32_t rr[4];
                ldm_x4(rr, Bs + np * (16 * ROWB) + kk * 32);
                bf[np * 2 + 0][0] = rr[0]; bf[np * 2 + 0][1] = rr[1];
                bf[np * 2 + 1][0] = rr[2]; bf[np * 2 + 1][1] = rr[3];
            }
#pragma unroll
            for (int mf = 0; mf < 2; mf++)
#pragma unroll
                for (int nf = 0; nf < 8; nf++)
                    mma_s8(acc[mf][nf], af[mf], bf[nf]);
        }
    }

    // ---- epilogue: per-row sumexp (dequant by 1/(SX*SB)) ----
    const int qid = lane >> 2;
    const int qlane = lane & 3;
#pragma unroll
    for (int mf = 0; mf < 2; mf++) {
#pragma unroll
        for (int h = 0; h < 2; h++) {
            int rl = warp_m * 32 + mf * 16 + qid + h * 8;
            int rg = row0 + rl;
            bool valid = rg < count;
            float s = 0.f;
#pragma unroll
            for (int nf = 0; nf < 8; nf++) {
                int cl = col0 + warp_n * 64 + nf * 8 + qlane * 2;
                if (cl < ncols)
                    s += __expf(__int2float_rn(acc[mf][nf][h * 2 + 0]) * INV_SCALE);
                if (cl + 1 < ncols)
                    s += __expf(__int2float_rn(acc[mf][nf][h * 2 + 1]) * INV_SCALE);
            }
            s += __shfl_xor_sync(0xffffffffu, s, 1);
            s += __shfl_xor_sync(0xffffffffu, s, 2);
            if (valid && qlane == 0) atomicAdd(&g_sumexp[stok[rl]], s);
        }
    }
}

// ---------------------------------------------------------------------------
// L4: exact fp32 target logit: g_tgt[t] = dot(x[t], logits[:, y[t]])
// ---------------------------------------------------------------------------
__global__ void k_tgt(const float* __restrict__ x,
                      const int* __restrict__ y,
                      const float* __restrict__ logits, int n, int vocab) {
    int warp = (blockIdx.x * blockDim.x + threadIdx.x) >> 5;
    int lane = threadIdx.x & 31;
    if (warp >= n) return;
    const int gy = y[warp];
    const float* xr = x + (size_t)warp * HID;
    float s = 0.f;
#pragma unroll 4
    for (int k = lane; k < HID; k += 32)
        s += xr[k] * logits[(size_t)k * vocab + gy];
#pragma unroll
    for (int m = 16; m; m >>= 1)
        s += __shfl_xor_sync(0xffffffffu, s, m);
    if (lane == 0) g_tgt[warp] = s;
}

// ---------------------------------------------------------------------------
// L5: finalize
// ---------------------------------------------------------------------------
__global__ void k_final(float* __restrict__ out, int n) {
    int t = blockIdx.x * blockDim.x + threadIdx.x;
    if (t >= n) return;
    out[t] = g_rownll[t] + logf(g_sumexp[t]) - g_tgt[t];
}

// ---------------------------------------------------------------------------
extern "C" void kernel_launch(void* const* d_in, const int* in_sizes, int n_in,
                              void* d_out, int out_size) {
    const float* x = (const float*)d_in[0];
    const int* y = (const int*)d_in[1];
    const float* Wc = (const float*)d_in[2];
    const float* logits = (const float*)d_in[3];
    float* out = (float*)d_out;

    int n = in_sizes[1];               // 4096
    int hidden = in_sizes[0] / n;      // 1024
    int vocab = in_sizes[3] / hidden;  // 50257

    cudaFuncSetAttribute(k_main_mma,
                         cudaFuncAttributeMaxDynamicSharedMemorySize, SMEM_DYN);

    // 0: B quantize (also zeros g_counts)
    k_convert_B<<<dim3((vocab + 31) / 32, hidden / 64), 256>>>(logits, vocab);
    // 1: cluster head + bucketing
    k_cluster_bucket<<<(n + 7) / 8, 256>>>(x, y, Wc, n);
    // 2: A quantize (bucketed)
    k_convert_x<<<dim3(n, NCL), 128>>>(x);
    // 3: main s8 GEMM  (ncu profiled slot)
    dim3 grid((20000 + 255) / 256, (n + 127) / 128, NCL);
    k_main_mma<<<grid, NTHR, SMEM_DYN>>>(vocab);
    // 4: exact target logits
    k_tgt<<<(n + 7) / 8, 256>>>(x, y, logits, n, vocab);
    // 5: finalize
    k_final<<<(n + 255) / 256, 256>>>(out, n);
}

// round 12
// speedup vs baseline: 2.0795x; 2.0795x over previous
#include <cuda_runtime.h>
#include <cuda_bf16.h>
#include <cuda_fp8.h>
#include <cstdint>

// ---------------------------------------------------------------------------
// FactorizedSoftmaxV2, R12: fp8 e4m3 mma.sync GEMM (R8/R9 mainloop, at the
// mma.sync throughput wall) + fused auxiliary pipeline.
//   nll[t] = (lse3 - s_cluster) + (log sumexp(z_fp8) - z_tgt_fp32)
// Launches:
//   0 k_convert_B : logits*64 -> e4m3 [vocab][1024]; zeros g_counts
//   1 k_prep      : per-token warp: cluster head + bucket slot + exact fp32
//                   target dot + x row quantization into bucketed g_A8
//   2 k_main_mma  : 128x256 CTA, warp 32x64, m16n8k32.e4m3, 3-stage cp.async
//   3 k_final     : nll assembly
// ---------------------------------------------------------------------------

#define MAX_TOK 4096
#define HID 1024
#define NCL 3
#define MAX_VOCAB 50257
#define BSCALE 64.0f
#define INV_BSCALE 0.015625f

__device__ int    g_order[NCL * MAX_TOK];
__device__ int    g_counts[NCL];
__device__ float  g_rownll[MAX_TOK];
__device__ float  g_sumexp[MAX_TOK];
__device__ float  g_tgt[MAX_TOK];
__device__ uint8_t g_A8[(size_t)NCL * MAX_TOK * HID];     // 12 MB (e4m3)
__device__ uint8_t g_B8[(size_t)MAX_VOCAB * HID];         // ~51 MB (e4m3)

__device__ __forceinline__ int cluster_of(int yy) {
    return yy < 20000 ? 0 : (yy < 40000 ? 1 : 2);
}

// ---------------- PTX helpers (baseline PTX only) ----------------
__device__ __forceinline__ uint32_t smem_u32(const void* p) {
    uint32_t a;
    asm("{ .reg .u64 t; cvta.to.shared.u64 t, %1; cvt.u32.u64 %0, t; }"
        : "=r"(a) : "l"(p));
    return a;
}
__device__ __forceinline__ void cp16(uint32_t dst, const void* src) {
    size_t g = __cvta_generic_to_global(src);
    asm volatile("cp.async.cg.shared.global [%0], [%1], 16;"
                 :: "r"(dst), "l"(g) : "memory");
}
#define CP_COMMIT() asm volatile("cp.async.commit_group;" ::: "memory")

__device__ __forceinline__ void ldm_x4(uint32_t* r, uint32_t addr) {
    asm volatile("ldmatrix.sync.aligned.m8n8.x4.shared.b16 {%0,%1,%2,%3}, [%4];"
                 : "=r"(r[0]), "=r"(r[1]), "=r"(r[2]), "=r"(r[3]) : "r"(addr));
}
__device__ __forceinline__ void mma_fp8(float* d, const uint32_t* a,
                                        const uint32_t* b) {
    asm volatile(
        "mma.sync.aligned.m16n8k32.row.col.f32.e4m3.e4m3.f32 "
        "{%0,%1,%2,%3}, {%4,%5,%6,%7}, {%8,%9}, {%0,%1,%2,%3};"
        : "+f"(d[0]), "+f"(d[1]), "+f"(d[2]), "+f"(d[3])
        : "r"(a[0]), "r"(a[1]), "r"(a[2]), "r"(a[3]), "r"(b[0]), "r"(b[1]));
}

__device__ __forceinline__ uint16_t f2_to_fp8x2(float a, float b) {
    return (uint16_t)__nv_cvt_float2_to_fp8x2(make_float2(a, b),
                                              __NV_SATFINITE, __NV_E4M3);
}

// ---------------------------------------------------------------------------
// L0: logits [1024][vocab] f32 -> g_B8 [vocab][1024] e4m3 (x64). Zeros counts.
// ---------------------------------------------------------------------------
__global__ void k_convert_B(const float* __restrict__ logits, int vocab) {
    __shared__ float tile[64][33];
    if (blockIdx.x == 0 && blockIdx.y == 0 && threadIdx.x < NCL)
        g_counts[threadIdx.x] = 0;
    const int nb = blockIdx.x * 32;
    const int kb = blockIdx.y * 64;
    const int tid = threadIdx.x;
#pragma unroll
    for (int j = 0; j < 8; j++) {
        int idx = tid + j * 256;
        int k = idx >> 5, n = idx & 31;
        tile[k][n] = (nb + n < vocab)
            ? logits[(size_t)(kb + k) * vocab + nb + n] : 0.f;
    }
    __syncthreads();
    const int n_loc = tid >> 3;
    const int kq = (tid & 7) * 8;
    const int n = nb + n_loc;
    if (n < vocab) {
        uint16_t w[4];
#pragma unroll
        for (int i = 0; i < 4; i++)
            w[i] = f2_to_fp8x2(tile[kq + i * 2][n_loc] * BSCALE,
                               tile[kq + i * 2 + 1][n_loc] * BSCALE);
        *(uint2*)(g_B8 + (size_t)n * HID + kb + kq) = *(uint2*)w;
    }
}

// ---------------------------------------------------------------------------
// L1: k_prep — one warp per token:
//  (a) 3 cluster-head dots + exact fp32 target dot (shared x reads)
//  (b) log-softmax over 3, bucket slot via atomic
//  (c) quantize x row into g_A8 at the bucketed position
// ---------------------------------------------------------------------------
__global__ void k_prep(const float* __restrict__ x,
                       const int* __restrict__ y,
                       const float* __restrict__ Wc,
                       const float* __restrict__ logits,
                       int n, int vocab) {
    int warp = (blockIdx.x * blockDim.x + threadIdx.x) >> 5;
    int lane = threadIdx.x & 31;
    if (warp >= n) return;
    const int gy = y[warp];
    const int cy = cluster_of(gy);
    const float* xr = x + (size_t)warp * HID;
    float s0 = 0.f, s1 = 0.f, s2 = 0.f, st = 0.f;
#pragma unroll 4
    for (int k = lane; k < HID; k += 32) {
        float xv = xr[k];
        s0 += xv * Wc[k];
        s1 += xv * Wc[HID + k];
        s2 += xv * Wc[2 * HID + k];
        st += xv * logits[(size_t)k * vocab + gy];
    }
#pragma unroll
    for (int m = 16; m; m >>= 1) {
        s0 += __shfl_xor_sync(0xffffffffu, s0, m);
        s1 += __shfl_xor_sync(0xffffffffu, s1, m);
        s2 += __shfl_xor_sync(0xffffffffu, s2, m);
        st += __shfl_xor_sync(0xffffffffu, st, m);
    }
    int slot = 0;
    if (lane == 0) {
        float mx = fmaxf(s0, fmaxf(s1, s2));
        float lse = logf(expf(s0 - mx) + expf(s1 - mx) + expf(s2 - mx)) + mx;
        float sc = (cy == 0) ? s0 : ((cy == 1) ? s1 : s2);
        g_rownll[warp] = lse - sc;
        g_sumexp[warp] = 0.f;
        g_tgt[warp] = st;
        slot = atomicAdd(&g_counts[cy], 1);
        g_order[cy * MAX_TOK + slot] = warp;
    }
    slot = __shfl_sync(0xffffffffu, slot, 0);
    // quantize this token's row into its bucketed position (8 floats/lane x 4)
    uint8_t* dst = g_A8 + (size_t)(cy * MAX_TOK + slot) * HID;
#pragma unroll
    for (int itq = 0; itq < 4; itq++) {
        int off = itq * 256 + lane * 8;
        float4 v0 = *(const float4*)(xr + off);
        float4 v1 = *(const float4*)(xr + off + 4);
        uint16_t w[4];
        w[0] = f2_to_fp8x2(v0.x, v0.y);
        w[1] = f2_to_fp8x2(v0.z, v0.w);
        w[2] = f2_to_fp8x2(v1.x, v1.y);
        w[3] = f2_to_fp8x2(v1.z, v1.w);
        *(uint2*)(dst + off) = *(uint2*)w;
    }
}

// ---------------------------------------------------------------------------
// L2: main GEMM. CTA 128(M)x256(N), BK=64 fp8, 512 threads (16 warps),
// warp tile 32x64 via m16n8k32.e4m3. 3-stage cp.async pipeline.
// Row layout: 80 B (64 data + 16 pad) -> conflict-free ldmatrix.
// ---------------------------------------------------------------------------
#define BK 64
#define ROWB 80
#define ABYTES (128 * ROWB)             // 10240
#define BBYTES (256 * ROWB)             // 20480
#define STAGE (ABYTES + BBYTES)         // 30720
#define SMEM_DYN (3 * STAGE)            // 92160
#define NTHR 512

struct TA { int abase, row0, count, l, col0, vocab; };

__device__ __forceinline__ void load_tile(uint32_t sb, int it, int stage,
                                          int tid, const TA& ta) {
    const int k0 = it * BK;
    const uint32_t As = sb + stage * STAGE;
    const uint32_t Bs = As + ABYTES;
    {
        int row = tid >> 2, cc = tid & 3;
        int rl = ta.row0 + row;
        int ridx = ta.abase + (rl < ta.count ? rl : ta.count - 1);
        cp16(As + row * ROWB + cc * 16,
             g_A8 + (size_t)ridx * HID + k0 + cc * 16);
    }
#pragma unroll
    for (int j = 0; j < 2; j++) {
        int q = tid + j * NTHR;
        int row = q >> 2, cc = q & 3;
        int col = ta.l + ta.col0 + row;
        if (col >= ta.vocab) col = ta.vocab - 1;
        cp16(Bs + row * ROWB + cc * 16,
             g_B8 + (size_t)col * HID + k0 + cc * 16);
    }
    CP_COMMIT();
}

__global__ __launch_bounds__(NTHR, 1)
void k_main_mma(int vocab) {
    extern __shared__ char dsm[];
    __shared__ int stok[128];

    const int c = blockIdx.z;
    const int l = (c == 0) ? 0 : ((c == 1) ? 20000 : 40000);
    const int r = (c == 0) ? 20000 : ((c == 1) ? 40000 : vocab);
    const int ncols = r - l;
    const int col0 = blockIdx.x * 256;
    if (col0 >= ncols) return;
    const int count = g_counts[c];
    const int row0 = blockIdx.y * 128;
    if (row0 >= count) return;
    const int abase = c * MAX_TOK;

    const int tid = threadIdx.x;
    const int lane = tid & 31;
    const int wid = tid >> 5;
    const int warp_m = wid & 3;      // 0..3  (32-row slab)
    const int warp_n = wid >> 2;     // 0..3  (64-col slab)

    const uint32_t sb = smem_u32(dsm);

    if (tid < 128) {
        int rl = row0 + tid;
        stok[tid] = g_order[abase + (rl < count ? rl : count - 1)];
    }
    __syncthreads();

    TA ta{abase, row0, count, l, col0, vocab};

    float acc[2][8][4];
#pragma unroll
    for (int i = 0; i < 2; i++)
#pragma unroll
        for (int j = 0; j < 8; j++)
#pragma unroll
            for (int q = 0; q < 4; q++) acc[i][j][q] = 0.f;

    load_tile(sb, 0, 0, tid, ta);
    load_tile(sb, 1, 1, tid, ta);

    const uint32_t a_off = (warp_m * 32 + (lane & 15)) * ROWB + (lane >> 4) * 16;
    const uint32_t b_off = (warp_n * 64 + ((lane >> 4) << 3) + (lane & 7)) * ROWB +
                           ((lane >> 3) & 1) * 16;

    const int KIT = HID / BK;  // 16
    for (int it = 0; it < KIT; it++) {
        if (it < KIT - 1)
            asm volatile("cp.async.wait_group 1;" ::: "memory");
        else
            asm volatile("cp.async.wait_group 0;" ::: "memory");
        __syncthreads();
        if (it + 2 < KIT) load_tile(sb, it + 2, (it + 2) % 3, tid, ta);

        const uint32_t As = sb + (it % 3) * STAGE + a_off;
        const uint32_t Bs = sb + (it % 3) * STAGE + ABYTES + b_off;
#pragma unroll
        for (int kk = 0; kk < 2; kk++) {    // 32 fp8 k-elems each
            uint32_t af[2][4], bf[8][2];
#pragma unroll
            for (int mf = 0; mf < 2; mf++)
                ldm_x4(af[mf], As + mf * (16 * ROWB) + kk * 32);
#pragma unroll
            for (int np = 0; np < 4; np++) {
                uint32_t rr[4];
                ldm_x4(rr, Bs + np * (16 * ROWB) + kk * 32);
                bf[np * 2 + 0][0] = rr[0]; bf[np * 2 + 0][1] = rr[1];
                bf[np * 2 + 1][0] = rr[2]; bf[np * 2 + 1][1] = rr[3];
            }
#pragma unroll
            for (int mf = 0; mf < 2; mf++)
#pragma unroll
                for (int nf = 0; nf < 8; nf++)
                    mma_fp8(acc[mf][nf], af[mf], bf[nf]);
        }
    }

    // ---- epilogue: per-row sumexp (scale by 1/64) ----
    const int qid = lane >> 2;
    const int qlane = lane & 3;
#pragma unroll
    for (int mf = 0; mf < 2; mf++) {
#pragma unroll
        for (int h = 0; h < 2; h++) {
            int rl = warp_m * 32 + mf * 16 + qid + h * 8;
            int rg = row0 + rl;
            bool valid = rg < count;
            float s = 0.f;
#pragma unroll
            for (int nf = 0; nf < 8; nf++) {
                int cl = col0 + warp_n * 64 + nf * 8 + qlane * 2;
                if (cl < ncols)
                    s += __expf(acc[mf][nf][h * 2 + 0] * INV_BSCALE);
                if (cl + 1 < ncols)
                    s += __expf(acc[mf][nf][h * 2 + 1] * INV_BSCALE);
            }
            s += __shfl_xor_sync(0xffffffffu, s, 1);
            s += __shfl_xor_sync(0xffffffffu, s, 2);
            if (valid && qlane == 0) atomicAdd(&g_sumexp[stok[rl]], s);
        }
    }
}

// ---------------------------------------------------------------------------
// L3: finalize
// ---------------------------------------------------------------------------
__global__ void k_final(float* __restrict__ out, int n) {
    int t = blockIdx.x * blockDim.x + threadIdx.x;
    if (t >= n) return;
    out[t] = g_rownll[t] + logf(g_sumexp[t]) - g_tgt[t];
}

// ---------------------------------------------------------------------------
extern "C" void kernel_launch(void* const* d_in, const int* in_sizes, int n_in,
                              void* d_out, int out_size) {
    const float* x = (const float*)d_in[0];
    const int* y = (const int*)d_in[1];
    const float* Wc = (const float*)d_in[2];
    const float* logits = (const float*)d_in[3];
    float* out = (float*)d_out;

    int n = in_sizes[1];               // 4096
    int hidden = in_sizes[0] / n;      // 1024
    int vocab = in_sizes[3] / hidden;  // 50257

    cudaFuncSetAttribute(k_main_mma,
                         cudaFuncAttributeMaxDynamicSharedMemorySize, SMEM_DYN);

    // 0: B quantize (also zeros g_counts)
    k_convert_B<<<dim3((vocab + 31) / 32, hidden / 64), 256>>>(logits, vocab);
    // 1: fused cluster head + bucketing + target dot + x quantization
    k_prep<<<(n + 7) / 8, 256>>>(x, y, Wc, logits, n, vocab);
    // 2: main fp8 GEMM
    dim3 grid((20000 + 255) / 256, (n + 127) / 128, NCL);
    k_main_mma<<<grid, NTHR, SMEM_DYN>>>(vocab);
    // 3: finalize
    k_final<<<(n + 255) / 256, 256>>>(out, n);
}